// round 5
// baseline (speedup 1.0000x reference)
#include <cuda_runtime.h>
#include <cuda_bf16.h>
#include <cstddef>

// ---------------------------------------------------------------------------
// StockPredictor: 2-layer LSTM (B=256, T=2048, D=1, H1=128, H2=64) + FC head.
// R4: 1024 threads/block, K-dimension split across thread-parts so ALL
// recurrent weights are register-resident (no spills, no weight LDS).
// ---------------------------------------------------------------------------

constexpr int T  = 2048;
constexpr int B  = 256;
constexpr int H1 = 128;
constexpr int G1 = 4 * H1;   // 512
constexpr int H2 = 64;
constexpr int G2 = 4 * H2;   // 256
constexpr int BB = 2;        // batch elems per block
constexpr int NBLK = B / BB; // 128 blocks

// scratch: h1 sequence, fp32  (256 MB)
__device__ float g_h1seq[(size_t)B * T * H1];

// ---------------------------------------------------------------------------
__device__ __forceinline__ void fma2(unsigned long long& acc,
                                     unsigned long long a,
                                     unsigned long long b) {
    asm("fma.rn.f32x2 %0, %1, %2, %0;" : "+l"(acc) : "l"(a), "l"(b));
}
__device__ __forceinline__ float f32x2_sum2(unsigned long long u,
                                            unsigned long long v) {
    unsigned long long s;
    asm("add.rn.f32x2 %0, %1, %2;" : "=l"(s) : "l"(u), "l"(v));
    float lo, hi;
    asm("mov.b64 {%0, %1}, %2;" : "=f"(lo), "=f"(hi) : "l"(s));
    return lo + hi;
}
__device__ __forceinline__ float sigmoid_fast(float x) {
    return __fdividef(1.0f, 1.0f + __expf(-x));
}
__device__ __forceinline__ float tanh_acc(float x) {
    return fmaf(2.0f, sigmoid_fast(2.0f * x), -1.0f);
}

// dot over N ulonglong2 (4 floats each) for both batches
template <int N>
__device__ __forceinline__ void dotN(const ulonglong2* __restrict__ w,
                                     const float* __restrict__ hA,
                                     const float* __restrict__ hB,
                                     unsigned long long& a0, unsigned long long& a1,
                                     unsigned long long& c0, unsigned long long& c1)
{
    const ulonglong2* pa = reinterpret_cast<const ulonglong2*>(hA);
    const ulonglong2* pb = reinterpret_cast<const ulonglong2*>(hB);
    #pragma unroll
    for (int i = 0; i < N; i++) {
        ulonglong2 wv = w[i];
        ulonglong2 p  = pa[i];
        ulonglong2 q  = pb[i];
        fma2(a0, wv.x, p.x); fma2(a1, wv.y, p.y);
        fma2(c0, wv.x, q.x); fma2(c1, wv.y, q.y);
    }
}

// ---------------------------------------------------------------------------
// Layer 1: 1024 threads = 512 gate rows x 2 K-halves of 64.
// All of W_hh1 register-resident (32 regs/thread).
// ---------------------------------------------------------------------------
__global__ __launch_bounds__(1024, 1)
void lstm1_kernel(const float* __restrict__ x,
                  const float* __restrict__ W_ih1,
                  const float* __restrict__ W_hh1,
                  const float* __restrict__ b_ih1,
                  const float* __restrict__ b_hh1)
{
    __shared__ float xs[BB * T];          // 4096
    __shared__ float hs[BB * H1];         // 256
    __shared__ float gs[BB * G1];         // 1024
    __shared__ float2 ps[2 * G1];         // [part][row] partials

    const int tid   = threadIdx.x;
    const int r     = tid & (G1 - 1);
    const int part  = tid >> 9;           // 0 or 1
    const int bbase = blockIdx.x * BB;

    // register weights: 64 floats = 16 ulonglong2
    ulonglong2 wr[16];
    {
        const ulonglong2* src =
            reinterpret_cast<const ulonglong2*>(W_hh1 + r * H1 + part * 64);
        #pragma unroll
        for (int j = 0; j < 16; j++) wr[j] = src[j];
    }
    const float wx   = W_ih1[r];
    const float bias = b_ih1[r] + b_hh1[r];

    for (int i = tid; i < BB * T; i += 1024)
        xs[i] = x[(size_t)bbase * T + i];
    if (tid < BB * H1) hs[tid] = 0.0f;
    __syncthreads();

    float c_state = 0.0f;  // valid for tid < 256

    const float* hseg0 = hs + part * 64;        // batch0 segment
    const float* hseg1 = hs + H1 + part * 64;   // batch1 segment
    const bool  is_g   = (r >= 2 * H1) && (r < 3 * H1);

    for (int t = 0; t < T; t++) {
        unsigned long long a0 = 0, a1 = 0, c0 = 0, c1 = 0;
        dotN<16>(wr, hseg0, hseg1, a0, a1, c0, c1);
        ps[part * G1 + r] = make_float2(f32x2_sum2(a0, a1), f32x2_sum2(c0, c1));
        __syncthreads();

        // finalize: thread-part p handles batch p
        {
            float2 u = ps[r];
            float2 v = ps[G1 + r];
            float partial = (part == 0) ? (u.x + v.x) : (u.y + v.y);
            float tot = partial + fmaf(xs[part * T + t], wx, bias);
            gs[part * G1 + r] = is_g ? tanh_acc(tot) : sigmoid_fast(tot);
        }
        __syncthreads();

        if (tid < BB * H1) {
            int bb = tid >> 7;
            int m  = tid & (H1 - 1);
            const float* gb = gs + bb * G1;
            float i_ = gb[m];
            float f_ = gb[H1 + m];
            float g_ = gb[2 * H1 + m];
            float o_ = gb[3 * H1 + m];
            c_state  = fmaf(f_, c_state, i_ * g_);
            float h  = o_ * tanh_acc(c_state);
            hs[tid]  = h;
            __stcs(&g_h1seq[((size_t)(bbase + bb) * T + t) * H1 + m], h);
        }
        __syncthreads();
    }
}

// ---------------------------------------------------------------------------
// Layer 2 + FC head: 1024 threads = 256 gate rows x 4 K-quarters of 48.
// K split: p0: h1[0,48)  p1: h1[48,96)  p2: h1[96,128)+h2[0,16)  p3: h2[16,64)
// All weights register-resident (24 regs/thread).
// ---------------------------------------------------------------------------
__global__ __launch_bounds__(1024, 1)
void lstm2_kernel(const float* __restrict__ W_ih2,
                  const float* __restrict__ W_hh2,
                  const float* __restrict__ b_ih2,
                  const float* __restrict__ b_hh2,
                  const float* __restrict__ W_fc1,
                  const float* __restrict__ b_fc1,
                  const float* __restrict__ W_fc2,
                  const float* __restrict__ b_fc2,
                  float* __restrict__ out)
{
    __shared__ float  h1s[2 * BB * H1];   // double buffer (512)
    __shared__ float  h2s[BB * H2];       // 128
    __shared__ float  gs[BB * G2];        // 512
    __shared__ float2 ps[4 * G2];         // [part][row] partials

    const int tid   = threadIdx.x;
    const int r     = tid & (G2 - 1);
    const int part  = tid >> 8;           // 0..3
    const int bbase = blockIdx.x * BB;

    // register weights: 48 floats = 12 ulonglong2
    ulonglong2 wr[12];
    if (part == 0) {
        const ulonglong2* s = reinterpret_cast<const ulonglong2*>(W_ih2 + r * H1);
        #pragma unroll
        for (int j = 0; j < 12; j++) wr[j] = s[j];
    } else if (part == 1) {
        const ulonglong2* s = reinterpret_cast<const ulonglong2*>(W_ih2 + r * H1 + 48);
        #pragma unroll
        for (int j = 0; j < 12; j++) wr[j] = s[j];
    } else if (part == 2) {
        const ulonglong2* sa = reinterpret_cast<const ulonglong2*>(W_ih2 + r * H1 + 96);
        const ulonglong2* sb = reinterpret_cast<const ulonglong2*>(W_hh2 + r * H2);
        #pragma unroll
        for (int j = 0; j < 8; j++) wr[j] = sa[j];
        #pragma unroll
        for (int j = 0; j < 4; j++) wr[8 + j] = sb[j];
    } else {
        const ulonglong2* s = reinterpret_cast<const ulonglong2*>(W_hh2 + r * H2 + 16);
        #pragma unroll
        for (int j = 0; j < 12; j++) wr[j] = s[j];
    }
    const float bias = b_ih2[r] + b_hh2[r];

    if (tid < BB * H2) h2s[tid] = 0.0f;
    if (tid < BB * H1) {   // preload h1 for t=0 into buffer 0
        int bb = tid >> 7, m = tid & (H1 - 1);
        h1s[tid] = __ldcs(&g_h1seq[((size_t)(bbase + bb) * T + 0) * H1 + m]);
    }
    __syncthreads();

    float c_state = 0.0f;  // valid for tid < 128
    const bool is_g = (r >= 2 * H2) && (r < 3 * H2);
    const int ld_bb = tid >> 7;           // part0 prefetch (tid<256)
    const int ld_m  = tid & (H1 - 1);

    for (int t = 0; t < T; t++) {
        const int cur = t & 1;
        const float* h1c = h1s + cur * BB * H1;

        // part0 threads prefetch next-step h1 (exactly 256 loads)
        float pre = 0.0f;
        if (part == 0 && t + 1 < T)
            pre = __ldcs(&g_h1seq[((size_t)(bbase + ld_bb) * T + (t + 1)) * H1 + ld_m]);

        unsigned long long a0 = 0, a1 = 0, c0 = 0, c1 = 0;
        if (part == 0) {
            dotN<12>(wr, h1c, h1c + H1, a0, a1, c0, c1);
        } else if (part == 1) {
            dotN<12>(wr, h1c + 48, h1c + H1 + 48, a0, a1, c0, c1);
        } else if (part == 2) {
            dotN<8>(wr, h1c + 96, h1c + H1 + 96, a0, a1, c0, c1);
            dotN<4>(wr + 8, h2s, h2s + H2, a0, a1, c0, c1);
        } else {
            dotN<12>(wr, h2s + 16, h2s + H2 + 16, a0, a1, c0, c1);
        }
        ps[part * G2 + r] = make_float2(f32x2_sum2(a0, a1), f32x2_sum2(c0, c1));
        __syncthreads();

        // finalize: parts 0,1 activate batch 0,1; part0 also stores prefetch
        if (part < 2) {
            float2 p0 = ps[r];
            float2 p1 = ps[G2 + r];
            float2 p2 = ps[2 * G2 + r];
            float2 p3 = ps[3 * G2 + r];
            float tot = bias + ((part == 0) ? (p0.x + p1.x + p2.x + p3.x)
                                            : (p0.y + p1.y + p2.y + p3.y));
            gs[part * G2 + r] = is_g ? tanh_acc(tot) : sigmoid_fast(tot);
            if (part == 0 && t + 1 < T)
                h1s[(cur ^ 1) * BB * H1 + tid] = pre;
        }
        __syncthreads();

        if (tid < BB * H2) {
            int bb = tid >> 6;
            int m  = tid & (H2 - 1);
            const float* gb = gs + bb * G2;
            float i_ = gb[m];
            float f_ = gb[H2 + m];
            float g_ = gb[2 * H2 + m];
            float o_ = gb[3 * H2 + m];
            c_state  = fmaf(f_, c_state, i_ * g_);
            h2s[tid] = o_ * tanh_acc(c_state);
        }
        __syncthreads();
    }

    // ---- FC head on final h2: [BB][64] -> [BB][25] -> [BB][1] ----
    if (tid < BB * 25) {
        int bb = tid / 25;
        int i  = tid - bb * 25;
        float a = b_fc1[i];
        #pragma unroll
        for (int k = 0; k < H2; k++)
            a = fmaf(W_fc1[i * H2 + k], h2s[bb * H2 + k], a);
        gs[bb * 32 + i] = a;
    }
    __syncthreads();
    if (tid < BB) {
        float a = b_fc2[0];
        #pragma unroll
        for (int i = 0; i < 25; i++)
            a = fmaf(W_fc2[i], gs[tid * 32 + i], a);
        out[bbase + tid] = a;
    }
}

// ---------------------------------------------------------------------------
extern "C" void kernel_launch(void* const* d_in, const int* in_sizes, int n_in,
                              void* d_out, int out_size)
{
    const float* x     = (const float*)d_in[0];
    const float* W_ih1 = (const float*)d_in[1];
    const float* W_hh1 = (const float*)d_in[2];
    const float* b_ih1 = (const float*)d_in[3];
    const float* b_hh1 = (const float*)d_in[4];
    const float* W_ih2 = (const float*)d_in[5];
    const float* W_hh2 = (const float*)d_in[6];
    const float* b_ih2 = (const float*)d_in[7];
    const float* b_hh2 = (const float*)d_in[8];
    const float* W_fc1 = (const float*)d_in[9];
    const float* b_fc1 = (const float*)d_in[10];
    const float* W_fc2 = (const float*)d_in[11];
    const float* b_fc2 = (const float*)d_in[12];
    float* out = (float*)d_out;

    lstm1_kernel<<<NBLK, 1024>>>(x, W_ih1, W_hh1, b_ih1, b_hh1);
    lstm2_kernel<<<NBLK, 1024>>>(W_ih2, W_hh2, b_ih2, b_hh2,
                                 W_fc1, b_fc1, W_fc2, b_fc2, out);
}

// round 7
// speedup vs baseline: 1.6561x; 1.6561x over previous
#include <cuda_runtime.h>
#include <cuda_bf16.h>
#include <cstddef>

// ---------------------------------------------------------------------------
// StockPredictor: 2-layer LSTM (B=256, T=2048, D=1, H1=128, H2=64) + FC head.
// R5 resubmit (R6 bench was an infra failure; kernel never measured).
//   lstm1: 512 thr, W_hh1 split 56 cols smem / 72 cols regs  (~100 regs)
//   lstm2: 512 thr, 2 parts x 256 rows, 48 reg + 48 smem floats (~80 regs),
//          2 barriers/step (activation fused into update threads).
// ---------------------------------------------------------------------------

constexpr int T  = 2048;
constexpr int B  = 256;
constexpr int H1 = 128;
constexpr int G1 = 4 * H1;   // 512
constexpr int H2 = 64;
constexpr int G2 = 4 * H2;   // 256
constexpr int BB = 2;
constexpr int NBLK = B / BB; // 128

// lstm1 split
constexpr int W1S_COLS  = 56;
constexpr int W1S_PITCH = 60;    // 15*16B (odd multiple of 16B) -> conflict-free

constexpr int SMEM1_F = G1 * W1S_PITCH + BB * T + BB * H1 + BB * G1; // 36096
constexpr size_t SMEM1_B = SMEM1_F * sizeof(float);                   // 144384

// lstm2 split
constexpr int W2S_PITCH = 52;    // 13*16B odd -> conflict-free
// layout (floats): h1s[512] | h2s[128] | ps[1024] | bias[256] | Ws2[512*52]
constexpr int L2_H1S  = 0;
constexpr int L2_H2S  = 512;
constexpr int L2_PS   = 640;          // 2 parts * 256 rows * float2
constexpr int L2_BIAS = 1664;
constexpr int L2_WS   = 1920;
constexpr int SMEM2_F = L2_WS + 512 * W2S_PITCH;                      // 28544
constexpr size_t SMEM2_B = SMEM2_F * sizeof(float);                   // 114176

// scratch: h1 sequence, fp32  (256 MB)
__device__ float g_h1seq[(size_t)B * T * H1];

// ---------------------------------------------------------------------------
__device__ __forceinline__ void fma2(unsigned long long& acc,
                                     unsigned long long a,
                                     unsigned long long b) {
    asm("fma.rn.f32x2 %0, %1, %2, %0;" : "+l"(acc) : "l"(a), "l"(b));
}
__device__ __forceinline__ float f32x2_sum2(unsigned long long u,
                                            unsigned long long v) {
    unsigned long long s;
    asm("add.rn.f32x2 %0, %1, %2;" : "=l"(s) : "l"(u), "l"(v));
    float lo, hi;
    asm("mov.b64 {%0, %1}, %2;" : "=f"(lo), "=f"(hi) : "l"(s));
    return lo + hi;
}
__device__ __forceinline__ float sigmoid_fast(float x) {
    return __fdividef(1.0f, 1.0f + __expf(-x));
}
__device__ __forceinline__ float tanh_acc(float x) {
    return fmaf(2.0f, sigmoid_fast(2.0f * x), -1.0f);
}

template <int N>
__device__ __forceinline__ void dotN(const ulonglong2* __restrict__ w,
                                     const float* __restrict__ hA,
                                     const float* __restrict__ hB,
                                     unsigned long long& a0, unsigned long long& a1,
                                     unsigned long long& c0, unsigned long long& c1)
{
    const ulonglong2* pa = reinterpret_cast<const ulonglong2*>(hA);
    const ulonglong2* pb = reinterpret_cast<const ulonglong2*>(hB);
    #pragma unroll
    for (int i = 0; i < N; i++) {
        ulonglong2 wv = w[i];
        ulonglong2 p  = pa[i];
        ulonglong2 q  = pb[i];
        fma2(a0, wv.x, p.x); fma2(a1, wv.y, p.y);
        fma2(c0, wv.x, q.x); fma2(c1, wv.y, q.y);
    }
}

// ---------------------------------------------------------------------------
// Layer 1: 512 threads, thread = gate row. 56 weight cols smem, 72 in regs.
// ---------------------------------------------------------------------------
__global__ __launch_bounds__(512, 1)
void lstm1_kernel(const float* __restrict__ x,
                  const float* __restrict__ W_ih1,
                  const float* __restrict__ W_hh1,
                  const float* __restrict__ b_ih1,
                  const float* __restrict__ b_hh1)
{
    extern __shared__ float sm[];
    float* Ws = sm;                       // [512][W1S_PITCH], cols [0,56)
    float* xs = Ws + G1 * W1S_PITCH;      // [BB][T]
    float* hs = xs + BB * T;              // [BB][H1]
    float* gs = hs + BB * H1;             // [BB][G1]

    const int tid   = threadIdx.x;
    const int bbase = blockIdx.x * BB;

    for (int i = tid; i < G1 * W1S_COLS; i += 512) {
        int r = i / W1S_COLS;
        int c = i - r * W1S_COLS;
        Ws[r * W1S_PITCH + c] = W_hh1[r * H1 + c];
    }
    // reg weights: cols [56,128) = 72 floats = 18 ulonglong2
    ulonglong2 wr[18];
    {
        const ulonglong2* src =
            reinterpret_cast<const ulonglong2*>(W_hh1 + tid * H1 + W1S_COLS);
        #pragma unroll
        for (int j = 0; j < 18; j++) wr[j] = src[j];
    }

    const float wx   = W_ih1[tid];
    const float bias = b_ih1[tid] + b_hh1[tid];

    for (int i = tid; i < BB * T; i += 512)
        xs[i] = x[(size_t)bbase * T + i];
    if (tid < BB * H1) hs[tid] = 0.0f;
    __syncthreads();

    float c_state = 0.0f;  // valid for tid < 256

    const ulonglong2* w2 = reinterpret_cast<const ulonglong2*>(Ws + tid * W1S_PITCH);
    const bool is_g = (tid >= 2 * H1) && (tid < 3 * H1);

    for (int t = 0; t < T; t++) {
        unsigned long long a0 = 0, a1 = 0, c0 = 0, c1 = 0;
        dotN<14>(w2, hs, hs + H1, a0, a1, c0, c1);                    // cols [0,56)
        dotN<18>(wr, hs + W1S_COLS, hs + H1 + W1S_COLS, a0, a1, c0, c1); // [56,128)

        float acc0 = fmaf(xs[t],     wx, bias) + f32x2_sum2(a0, a1);
        float acc1 = fmaf(xs[T + t], wx, bias) + f32x2_sum2(c0, c1);

        float v0, v1;
        if (is_g) { v0 = tanh_acc(acc0);     v1 = tanh_acc(acc1); }
        else      { v0 = sigmoid_fast(acc0); v1 = sigmoid_fast(acc1); }
        gs[tid]      = v0;
        gs[G1 + tid] = v1;
        __syncthreads();

        if (tid < BB * H1) {
            int bb = tid >> 7;
            int m  = tid & (H1 - 1);
            const float* gb = gs + bb * G1;
            float i_ = gb[m];
            float f_ = gb[H1 + m];
            float g_ = gb[2 * H1 + m];
            float o_ = gb[3 * H1 + m];
            c_state  = fmaf(f_, c_state, i_ * g_);
            float h  = o_ * tanh_acc(c_state);
            hs[tid]  = h;
            __stcs(&g_h1seq[((size_t)(bbase + bb) * T + t) * H1 + m], h);
        }
        __syncthreads();
    }
}

// ---------------------------------------------------------------------------
// Layer 2 + FC head: 512 threads. r = tid&255, part = tid>>8.
// part0 K: h1[0,96).   regs h1[0,48),    smem h1[48,96).
// part1 K: h1[96,128)+h2[0,64). regs h1[96,128)+h2[0,16), smem h2[16,64).
// Update threads (tid<128) read raw partials, apply activations. 2 barriers.
// ---------------------------------------------------------------------------
__global__ __launch_bounds__(512, 1)
void lstm2_kernel(const float* __restrict__ W_ih2,
                  const float* __restrict__ W_hh2,
                  const float* __restrict__ b_ih2,
                  const float* __restrict__ b_hh2,
                  const float* __restrict__ W_fc1,
                  const float* __restrict__ b_fc1,
                  const float* __restrict__ W_fc2,
                  const float* __restrict__ b_fc2,
                  float* __restrict__ out)
{
    extern __shared__ float sm[];
    float*  h1s  = sm + L2_H1S;           // [2][BB][H1] double buffer
    float*  h2s  = sm + L2_H2S;           // [BB][H2]
    float2* ps   = reinterpret_cast<float2*>(sm + L2_PS);  // [2 parts][G2]
    float*  bsm  = sm + L2_BIAS;          // [G2] combined bias
    float*  Ws2  = sm + L2_WS;            // [512][W2S_PITCH]

    const int tid   = threadIdx.x;
    const int r     = tid & (G2 - 1);
    const int part  = tid >> 8;           // 0 or 1
    const int bbase = blockIdx.x * BB;

    // smem weight tail (48 floats/thread, row tid)
    {
        float* wrow = Ws2 + tid * W2S_PITCH;
        const float* src = (part == 0) ? (W_ih2 + r * H1 + 48)
                                       : (W_hh2 + r * H2 + 16);
        #pragma unroll
        for (int j = 0; j < 48; j += 4)
            *reinterpret_cast<float4*>(wrow + j) =
                *reinterpret_cast<const float4*>(src + j);
    }
    // reg weights: 48 floats = 12 ulonglong2
    ulonglong2 wr[12];
    if (part == 0) {
        const ulonglong2* s = reinterpret_cast<const ulonglong2*>(W_ih2 + r * H1);
        #pragma unroll
        for (int j = 0; j < 12; j++) wr[j] = s[j];
    } else {
        const ulonglong2* sa = reinterpret_cast<const ulonglong2*>(W_ih2 + r * H1 + 96);
        const ulonglong2* sb = reinterpret_cast<const ulonglong2*>(W_hh2 + r * H2);
        #pragma unroll
        for (int j = 0; j < 8; j++) wr[j] = sa[j];
        #pragma unroll
        for (int j = 0; j < 4; j++) wr[8 + j] = sb[j];
    }
    if (tid < G2) bsm[tid] = b_ih2[tid] + b_hh2[tid];
    if (tid < BB * H2) h2s[tid] = 0.0f;
    if (tid < BB * H1) {
        int bb = tid >> 7, m = tid & (H1 - 1);
        h1s[tid] = __ldcs(&g_h1seq[((size_t)(bbase + bb) * T + 0) * H1 + m]);
    }
    __syncthreads();

    float c_state = 0.0f;  // valid for tid < 128
    const int ld_bb = (tid >> 7) & 1;     // part1 prefetch (tid-256 in [0,256))
    const int ld_m  = tid & (H1 - 1);
    const ulonglong2* ws =
        reinterpret_cast<const ulonglong2*>(Ws2 + tid * W2S_PITCH);

    for (int t = 0; t < T; t++) {
        const int cur = t & 1;
        const float* h1c = h1s + cur * BB * H1;

        float pre = 0.0f;
        if (part == 1 && t + 1 < T)
            pre = __ldcs(&g_h1seq[((size_t)(bbase + ld_bb) * T + (t + 1)) * H1 + ld_m]);

        unsigned long long a0 = 0, a1 = 0, c0 = 0, c1 = 0;
        if (part == 0) {
            dotN<12>(wr, h1c,      h1c + H1,      a0, a1, c0, c1);  // h1[0,48)
            dotN<12>(ws, h1c + 48, h1c + H1 + 48, a0, a1, c0, c1);  // h1[48,96)
        } else {
            dotN<8>(wr,     h1c + 96, h1c + H1 + 96, a0, a1, c0, c1); // h1[96,128)
            dotN<4>(wr + 8, h2s,      h2s + H2,      a0, a1, c0, c1); // h2[0,16)
            dotN<12>(ws,    h2s + 16, h2s + H2 + 16, a0, a1, c0, c1); // h2[16,64)
        }
        ps[part * G2 + r] = make_float2(f32x2_sum2(a0, a1), f32x2_sum2(c0, c1));
        if (part == 1 && t + 1 < T)
            h1s[(cur ^ 1) * BB * H1 + (tid - G2)] = pre;
        __syncthreads();

        // update threads: read raw partials for all 4 gates, activate, update
        if (tid < BB * H2) {
            int bb = tid >> 6;
            int m  = tid & (H2 - 1);
            float gate[4];
            #pragma unroll
            for (int gidx = 0; gidx < 4; gidx++) {
                int row = gidx * H2 + m;
                float2 u = ps[row];
                float2 v = ps[G2 + row];
                gate[gidx] = bsm[row] + ((bb == 0) ? (u.x + v.x) : (u.y + v.y));
            }
            float i_ = sigmoid_fast(gate[0]);
            float f_ = sigmoid_fast(gate[1]);
            float g_ = tanh_acc(gate[2]);
            float o_ = sigmoid_fast(gate[3]);
            c_state  = fmaf(f_, c_state, i_ * g_);
            h2s[tid] = o_ * tanh_acc(c_state);
        }
        __syncthreads();
    }

    // ---- FC head on final h2: [BB][64] -> [BB][25] -> [BB][1] ----
    float* stage = sm + L2_PS;  // reuse ps region
    if (tid < BB * 25) {
        int bb = tid / 25;
        int i  = tid - bb * 25;
        float a = b_fc1[i];
        #pragma unroll
        for (int k = 0; k < H2; k++)
            a = fmaf(W_fc1[i * H2 + k], h2s[bb * H2 + k], a);
        stage[bb * 32 + i] = a;
    }
    __syncthreads();
    if (tid < BB) {
        float a = b_fc2[0];
        #pragma unroll
        for (int i = 0; i < 25; i++)
            a = fmaf(W_fc2[i], stage[tid * 32 + i], a);
        out[bbase + tid] = a;
    }
}

// ---------------------------------------------------------------------------
extern "C" void kernel_launch(void* const* d_in, const int* in_sizes, int n_in,
                              void* d_out, int out_size)
{
    const float* x     = (const float*)d_in[0];
    const float* W_ih1 = (const float*)d_in[1];
    const float* W_hh1 = (const float*)d_in[2];
    const float* b_ih1 = (const float*)d_in[3];
    const float* b_hh1 = (const float*)d_in[4];
    const float* W_ih2 = (const float*)d_in[5];
    const float* W_hh2 = (const float*)d_in[6];
    const float* b_ih2 = (const float*)d_in[7];
    const float* b_hh2 = (const float*)d_in[8];
    const float* W_fc1 = (const float*)d_in[9];
    const float* b_fc1 = (const float*)d_in[10];
    const float* W_fc2 = (const float*)d_in[11];
    const float* b_fc2 = (const float*)d_in[12];
    float* out = (float*)d_out;

    static bool attr_done = false;
    if (!attr_done) {
        cudaFuncSetAttribute(lstm1_kernel,
                             cudaFuncAttributeMaxDynamicSharedMemorySize, (int)SMEM1_B);
        cudaFuncSetAttribute(lstm2_kernel,
                             cudaFuncAttributeMaxDynamicSharedMemorySize, (int)SMEM2_B);
        attr_done = true;
    }

    lstm1_kernel<<<NBLK, 512, SMEM1_B>>>(x, W_ih1, W_hh1, b_ih1, b_hh1);
    lstm2_kernel<<<NBLK, 512, SMEM2_B>>>(W_ih2, W_hh2, b_ih2, b_hh2,
                                         W_fc1, b_fc1, W_fc2, b_fc2, out);
}

// round 8
// speedup vs baseline: 1.6569x; 1.0005x over previous
#include <cuda_runtime.h>
#include <cuda_bf16.h>
#include <cstddef>

// ---------------------------------------------------------------------------
// StockPredictor: 2-layer LSTM (B=256, T=2048, D=1, H1=128, H2=64) + FC head.
// R8: lstm1 = R2 version (best measured). lstm2 rewritten: unified code path
// over concatenated state hcat = [h1(128) | h2(64)], all 96 weight floats in
// registers, 2 accumulator chains, zero weight-LDS.
// ---------------------------------------------------------------------------

constexpr int T  = 2048;
constexpr int B  = 256;
constexpr int H1 = 128;
constexpr int G1 = 4 * H1;   // 512
constexpr int H2 = 64;
constexpr int G2 = 4 * H2;   // 256
constexpr int BB = 2;
constexpr int NBLK = B / BB; // 128
constexpr int HC = H1 + H2;  // 192 concatenated state width

// lstm1 split (R2 config: 64 smem cols / 64 reg floats)
constexpr int W1S_COLS  = 64;
constexpr int W1S_PITCH = 68;    // 17*16B odd -> conflict-free LDS.128

constexpr int SMEM1_F = G1 * W1S_PITCH + BB * T + BB * H1 + BB * G1; // 40192
constexpr size_t SMEM1_B = SMEM1_F * sizeof(float);                   // 160768

// scratch: h1 sequence, fp32  (256 MB)
__device__ float g_h1seq[(size_t)B * T * H1];

// ---------------------------------------------------------------------------
__device__ __forceinline__ void fma2(unsigned long long& acc,
                                     unsigned long long a,
                                     unsigned long long b) {
    asm("fma.rn.f32x2 %0, %1, %2, %0;" : "+l"(acc) : "l"(a), "l"(b));
}
__device__ __forceinline__ float f32x2_sum1(unsigned long long u) {
    float lo, hi;
    asm("mov.b64 {%0, %1}, %2;" : "=f"(lo), "=f"(hi) : "l"(u));
    return lo + hi;
}
__device__ __forceinline__ float f32x2_sum2(unsigned long long u,
                                            unsigned long long v) {
    unsigned long long s;
    asm("add.rn.f32x2 %0, %1, %2;" : "=l"(s) : "l"(u), "l"(v));
    return f32x2_sum1(s);
}
__device__ __forceinline__ float sigmoid_fast(float x) {
    return __fdividef(1.0f, 1.0f + __expf(-x));
}
__device__ __forceinline__ float tanh_acc(float x) {
    return fmaf(2.0f, sigmoid_fast(2.0f * x), -1.0f);
}

template <int N>
__device__ __forceinline__ void dotN(const ulonglong2* __restrict__ w,
                                     const float* __restrict__ hA,
                                     const float* __restrict__ hB,
                                     unsigned long long& a0, unsigned long long& a1,
                                     unsigned long long& c0, unsigned long long& c1)
{
    const ulonglong2* pa = reinterpret_cast<const ulonglong2*>(hA);
    const ulonglong2* pb = reinterpret_cast<const ulonglong2*>(hB);
    #pragma unroll
    for (int i = 0; i < N; i++) {
        ulonglong2 wv = w[i];
        ulonglong2 p  = pa[i];
        ulonglong2 q  = pb[i];
        fma2(a0, wv.x, p.x); fma2(a1, wv.y, p.y);
        fma2(c0, wv.x, q.x); fma2(c1, wv.y, q.y);
    }
}

// ---------------------------------------------------------------------------
// Layer 1 (R2 version): 512 threads, thread = gate row, 64 smem / 64 reg cols.
// ---------------------------------------------------------------------------
__global__ __launch_bounds__(512, 1)
void lstm1_kernel(const float* __restrict__ x,
                  const float* __restrict__ W_ih1,
                  const float* __restrict__ W_hh1,
                  const float* __restrict__ b_ih1,
                  const float* __restrict__ b_hh1)
{
    extern __shared__ float sm[];
    float* Ws = sm;                       // [512][W1S_PITCH], cols [0,64)
    float* xs = Ws + G1 * W1S_PITCH;      // [BB][T]
    float* hs = xs + BB * T;              // [BB][H1]
    float* gs = hs + BB * H1;             // [BB][G1]

    const int tid   = threadIdx.x;
    const int bbase = blockIdx.x * BB;

    for (int i = tid; i < G1 * W1S_COLS; i += 512) {
        int r = i >> 6;
        int c = i & 63;
        Ws[r * W1S_PITCH + c] = W_hh1[r * H1 + c];
    }
    ulonglong2 wr[16];   // cols [64,128)
    {
        const ulonglong2* src =
            reinterpret_cast<const ulonglong2*>(W_hh1 + tid * H1 + W1S_COLS);
        #pragma unroll
        for (int j = 0; j < 16; j++) wr[j] = src[j];
    }

    const float wx   = W_ih1[tid];
    const float bias = b_ih1[tid] + b_hh1[tid];

    for (int i = tid; i < BB * T; i += 512)
        xs[i] = x[(size_t)bbase * T + i];
    if (tid < BB * H1) hs[tid] = 0.0f;
    __syncthreads();

    float c_state = 0.0f;  // valid for tid < 256

    const ulonglong2* w2 = reinterpret_cast<const ulonglong2*>(Ws + tid * W1S_PITCH);
    const bool is_g = (tid >= 2 * H1) && (tid < 3 * H1);

    for (int t = 0; t < T; t++) {
        unsigned long long a0 = 0, a1 = 0, c0 = 0, c1 = 0;
        dotN<16>(w2, hs,            hs + H1,            a0, a1, c0, c1); // [0,64)
        dotN<16>(wr, hs + W1S_COLS, hs + H1 + W1S_COLS, a0, a1, c0, c1); // [64,128)

        float acc0 = fmaf(xs[t],     wx, bias) + f32x2_sum2(a0, a1);
        float acc1 = fmaf(xs[T + t], wx, bias) + f32x2_sum2(c0, c1);

        float v0, v1;
        if (is_g) { v0 = tanh_acc(acc0);     v1 = tanh_acc(acc1); }
        else      { v0 = sigmoid_fast(acc0); v1 = sigmoid_fast(acc1); }
        gs[tid]      = v0;
        gs[G1 + tid] = v1;
        __syncthreads();

        if (tid < BB * H1) {
            int bb = tid >> 7;
            int m  = tid & (H1 - 1);
            const float* gb = gs + bb * G1;
            float i_ = gb[m];
            float f_ = gb[H1 + m];
            float g_ = gb[2 * H1 + m];
            float o_ = gb[3 * H1 + m];
            c_state  = fmaf(f_, c_state, i_ * g_);
            float h  = o_ * tanh_acc(c_state);
            hs[tid]  = h;
            __stcs(&g_h1seq[((size_t)(bbase + bb) * T + t) * H1 + m], h);
        }
        __syncthreads();
    }
}

// ---------------------------------------------------------------------------
// Layer 2 + FC head: 512 threads, r = tid&255, part = tid>>8.
// State concatenated: hcat[buf][bb][HC] = h1[0..128) | h2[128..192).
// part p covers K = [p*96, p*96+96) with IDENTICAL code.
// All 96 weight floats per thread in registers; 2 accumulator chains.
// ---------------------------------------------------------------------------
__global__ __launch_bounds__(512, 1)
void lstm2_kernel(const float* __restrict__ W_ih2,
                  const float* __restrict__ W_hh2,
                  const float* __restrict__ b_ih2,
                  const float* __restrict__ b_hh2,
                  const float* __restrict__ W_fc1,
                  const float* __restrict__ b_fc1,
                  const float* __restrict__ W_fc2,
                  const float* __restrict__ b_fc2,
                  float* __restrict__ out)
{
    __shared__ float  hcat[2][BB][HC];    // double-buffered concat state
    __shared__ float2 ps[2][G2];          // per-part partials
    __shared__ float  bsm[G2];            // combined bias
    __shared__ float  stage[BB * 32];     // FC staging

    const int tid   = threadIdx.x;
    const int r     = tid & (G2 - 1);
    const int part  = tid >> 8;           // 0 or 1
    const int koff  = part * 96;
    const int bbase = blockIdx.x * BB;

    // concatenated weight row: wcat[r][0:128) = W_ih2[r], wcat[r][128:192) = W_hh2[r]
    // this thread holds wcat[r][koff : koff+96) = 24 ulonglong2 (96 regs)
    ulonglong2 wr[24];
    if (part == 0) {
        const ulonglong2* s = reinterpret_cast<const ulonglong2*>(W_ih2 + r * H1);
        #pragma unroll
        for (int j = 0; j < 24; j++) wr[j] = s[j];
    } else {
        const ulonglong2* sa = reinterpret_cast<const ulonglong2*>(W_ih2 + r * H1 + 96);
        const ulonglong2* sb = reinterpret_cast<const ulonglong2*>(W_hh2 + r * H2);
        #pragma unroll
        for (int j = 0; j < 8; j++) wr[j] = sa[j];
        #pragma unroll
        for (int j = 0; j < 16; j++) wr[8 + j] = sb[j];
    }

    if (tid < G2) bsm[tid] = b_ih2[tid] + b_hh2[tid];
    // init state buffer 0: h1(t=0) + h2=0
    if (tid < BB * H1) {
        int bb = tid >> 7, m = tid & (H1 - 1);
        hcat[0][bb][m] = __ldcs(&g_h1seq[((size_t)(bbase + bb) * T + 0) * H1 + m]);
    }
    if (tid < BB * H2) {
        int bb = tid >> 6, m = tid & (H2 - 1);
        hcat[0][bb][H1 + m] = 0.0f;
    }
    __syncthreads();

    float c_state = 0.0f;  // valid for tid < 128
    const int ld_bb = (tid >> 7) & 1;     // part1 prefetch mapping (tid-256)
    const int ld_m  = tid & (H1 - 1);

    for (int t = 0; t < T; t++) {
        const int cur = t & 1;
        const int nxt = cur ^ 1;

        // part1 threads prefetch next-step h1 into the other buffer
        float pre = 0.0f;
        if (part == 1 && t + 1 < T)
            pre = __ldcs(&g_h1seq[((size_t)(bbase + ld_bb) * T + (t + 1)) * H1 + ld_m]);

        // unified dot: K = [koff, koff+96) of concatenated state, both batches
        unsigned long long a0 = 0, a1 = 0, c0 = 0, c1 = 0;
        dotN<24>(wr, &hcat[cur][0][koff], &hcat[cur][1][koff], a0, a1, c0, c1);
        ps[part][r] = make_float2(f32x2_sum2(a0, a1), f32x2_sum2(c0, c1));

        if (part == 1 && t + 1 < T)
            hcat[nxt][ld_bb][ld_m] = pre;
        __syncthreads();

        // update threads: combine partials, activate, update c/h2 into NEXT buffer
        if (tid < BB * H2) {
            int bb = tid >> 6;
            int m  = tid & (H2 - 1);
            float gate[4];
            #pragma unroll
            for (int gidx = 0; gidx < 4; gidx++) {
                int row = gidx * H2 + m;
                float2 u = ps[0][row];
                float2 v = ps[1][row];
                gate[gidx] = bsm[row] + ((bb == 0) ? (u.x + v.x) : (u.y + v.y));
            }
            float i_ = sigmoid_fast(gate[0]);
            float f_ = sigmoid_fast(gate[1]);
            float g_ = tanh_acc(gate[2]);
            float o_ = sigmoid_fast(gate[3]);
            c_state  = fmaf(f_, c_state, i_ * g_);
            float h2 = o_ * tanh_acc(c_state);
            hcat[nxt][bb][H1 + m] = h2;
            if (t == T - 1) hcat[cur][bb][H1 + m] = h2;  // final h2 for FC head
        }
        __syncthreads();
    }

    // ---- FC head on final h2 (in hcat[(T-1)&1][bb][H1..]): -> [BB][25] -> [BB][1] ----
    const int fin = (T - 1) & 1;
    if (tid < BB * 25) {
        int bb = tid / 25;
        int i  = tid - bb * 25;
        float a = b_fc1[i];
        #pragma unroll
        for (int k = 0; k < H2; k++)
            a = fmaf(W_fc1[i * H2 + k], hcat[fin][bb][H1 + k], a);
        stage[bb * 32 + i] = a;
    }
    __syncthreads();
    if (tid < BB) {
        float a = b_fc2[0];
        #pragma unroll
        for (int i = 0; i < 25; i++)
            a = fmaf(W_fc2[i], stage[tid * 32 + i], a);
        out[bbase + tid] = a;
    }
}

// ---------------------------------------------------------------------------
extern "C" void kernel_launch(void* const* d_in, const int* in_sizes, int n_in,
                              void* d_out, int out_size)
{
    const float* x     = (const float*)d_in[0];
    const float* W_ih1 = (const float*)d_in[1];
    const float* W_hh1 = (const float*)d_in[2];
    const float* b_ih1 = (const float*)d_in[3];
    const float* b_hh1 = (const float*)d_in[4];
    const float* W_ih2 = (const float*)d_in[5];
    const float* W_hh2 = (const float*)d_in[6];
    const float* b_ih2 = (const float*)d_in[7];
    const float* b_hh2 = (const float*)d_in[8];
    const float* W_fc1 = (const float*)d_in[9];
    const float* b_fc1 = (const float*)d_in[10];
    const float* W_fc2 = (const float*)d_in[11];
    const float* b_fc2 = (const float*)d_in[12];
    float* out = (float*)d_out;

    static bool attr_done = false;
    if (!attr_done) {
        cudaFuncSetAttribute(lstm1_kernel,
                             cudaFuncAttributeMaxDynamicSharedMemorySize, (int)SMEM1_B);
        attr_done = true;
    }

    lstm1_kernel<<<NBLK, 512, SMEM1_B>>>(x, W_ih1, W_hh1, b_ih1, b_hh1);
    lstm2_kernel<<<NBLK, 512>>>(W_ih2, W_hh2, b_ih2, b_hh2,
                                W_fc1, b_fc1, W_fc2, b_fc2, out);
}

// round 9
// speedup vs baseline: 1.8594x; 1.1222x over previous
#include <cuda_runtime.h>
#include <cuda_bf16.h>
#include <cstddef>

// ---------------------------------------------------------------------------
// StockPredictor: 2-layer LSTM (B=256, T=2048, D=1, H1=128, H2=64) + FC head.
// R9: single-kernel producer/consumer pipeline.
//   Blocks 0-63:  layer-1 producers, 4 batch elems each, 256 thr (2 rows/thr,
//                 64 reg + 64 smem weight floats per row).
//   Blocks 64-127: layer-2 consumers + FC head, 4 batch elems each, 256 thr
//                 (1 row/thr over concat K=192: 160 reg + 32 smem floats).
// h1 flows through g_h1seq; per-producer progress flag with release/acquire;
// end-of-kernel handshake resets flags so graph replays are identical.
// ---------------------------------------------------------------------------

constexpr int T  = 2048;
constexpr int B  = 256;
constexpr int H1 = 128;
constexpr int G1 = 4 * H1;   // 512
constexpr int H2 = 64;
constexpr int G2 = 4 * H2;   // 256
constexpr int NP = 64;       // producer blocks
constexpr int NC = 64;       // consumer blocks
constexpr int BBP = 4;       // batch elems per block

// Producer smem layout (float offsets)
constexpr int P_PITCH = 68;                 // 17*16B odd -> conflict-free LDS.128
constexpr int P_WS  = 0;                    // [512][68]
constexpr int P_XS  = G1 * P_PITCH;         // 34816  [4][2048]
constexpr int P_HS  = P_XS + BBP * T;       // 43008  [4][128]
constexpr int P_GS  = P_HS + BBP * H1;      // 43520  [4][512]
constexpr int P_END = P_GS + BBP * G1;      // 45568 floats = 182272 B

// Consumer smem layout (float offsets)
constexpr int C_PITCH = 36;                 // 9*16B odd
constexpr int C_WS   = 0;                   // [256][36]
constexpr int C_HC   = G2 * C_PITCH;        // 9216   hcat[4][192]
constexpr int C_GS   = C_HC + BBP * 192;    // 9984   [4][256]
constexpr int C_BS   = C_GS + BBP * G2;     // 11008  [256]
constexpr int C_ST   = C_BS + G2;           // 11264  [4][32] FC staging
constexpr int C_END  = C_ST + BBP * 32;

constexpr size_t SMEM_MAX = (size_t)P_END * sizeof(float);  // 182272

// scratch + sync (zero-initialized at module load; reset by end handshake)
__device__ float g_h1seq[(size_t)B * T * H1];
__device__ int   g_flag[NP];
__device__ int   g_done[NC];

// ---------------------------------------------------------------------------
__device__ __forceinline__ void fma2(unsigned long long& acc,
                                     unsigned long long a,
                                     unsigned long long b) {
    asm("fma.rn.f32x2 %0, %1, %2, %0;" : "+l"(acc) : "l"(a), "l"(b));
}
__device__ __forceinline__ float f32x2_sum2(unsigned long long u,
                                            unsigned long long v) {
    unsigned long long s;
    asm("add.rn.f32x2 %0, %1, %2;" : "=l"(s) : "l"(u), "l"(v));
    float lo, hi;
    asm("mov.b64 {%0, %1}, %2;" : "=f"(lo), "=f"(hi) : "l"(s));
    return lo + hi;
}
__device__ __forceinline__ float sigmoid_fast(float x) {
    return __fdividef(1.0f, 1.0f + __expf(-x));
}
__device__ __forceinline__ float tanh_acc(float x) {
    return fmaf(2.0f, sigmoid_fast(2.0f * x), -1.0f);
}
__device__ __forceinline__ int ld_acquire(const int* p) {
    int v;
    asm volatile("ld.acquire.gpu.global.b32 %0, [%1];" : "=r"(v) : "l"(p) : "memory");
    return v;
}
__device__ __forceinline__ void st_release(int* p, int v) {
    asm volatile("st.release.gpu.global.b32 [%0], %1;" :: "l"(p), "r"(v) : "memory");
}

// 1 weight row x 4 batch h streams (8 fma2 / iter)
template <int N>
__device__ __forceinline__ void dot4(const ulonglong2* __restrict__ w,
                                     const float* h0, const float* h1,
                                     const float* h2, const float* h3,
                                     unsigned long long* acc /*[8]*/)
{
    const ulonglong2* p0 = reinterpret_cast<const ulonglong2*>(h0);
    const ulonglong2* p1 = reinterpret_cast<const ulonglong2*>(h1);
    const ulonglong2* p2 = reinterpret_cast<const ulonglong2*>(h2);
    const ulonglong2* p3 = reinterpret_cast<const ulonglong2*>(h3);
    #pragma unroll
    for (int i = 0; i < N; i++) {
        ulonglong2 wv = w[i];
        ulonglong2 q0 = p0[i], q1 = p1[i], q2 = p2[i], q3 = p3[i];
        fma2(acc[0], wv.x, q0.x); fma2(acc[1], wv.y, q0.y);
        fma2(acc[2], wv.x, q1.x); fma2(acc[3], wv.y, q1.y);
        fma2(acc[4], wv.x, q2.x); fma2(acc[5], wv.y, q2.y);
        fma2(acc[6], wv.x, q3.x); fma2(acc[7], wv.y, q3.y);
    }
}

// 2 weight rows x 4 batch h streams (16 fma2 / iter); h loaded once
template <int N>
__device__ __forceinline__ void dot4x2(const ulonglong2* __restrict__ wA,
                                       const ulonglong2* __restrict__ wB,
                                       const float* h0, const float* h1,
                                       const float* h2, const float* h3,
                                       unsigned long long* acc /*[16]*/)
{
    const ulonglong2* p0 = reinterpret_cast<const ulonglong2*>(h0);
    const ulonglong2* p1 = reinterpret_cast<const ulonglong2*>(h1);
    const ulonglong2* p2 = reinterpret_cast<const ulonglong2*>(h2);
    const ulonglong2* p3 = reinterpret_cast<const ulonglong2*>(h3);
    #pragma unroll
    for (int i = 0; i < N; i++) {
        ulonglong2 wa = wA[i], wb = wB[i];
        ulonglong2 q0 = p0[i], q1 = p1[i], q2 = p2[i], q3 = p3[i];
        fma2(acc[0],  wa.x, q0.x); fma2(acc[1],  wa.y, q0.y);
        fma2(acc[2],  wa.x, q1.x); fma2(acc[3],  wa.y, q1.y);
        fma2(acc[4],  wa.x, q2.x); fma2(acc[5],  wa.y, q2.y);
        fma2(acc[6],  wa.x, q3.x); fma2(acc[7],  wa.y, q3.y);
        fma2(acc[8],  wb.x, q0.x); fma2(acc[9],  wb.y, q0.y);
        fma2(acc[10], wb.x, q1.x); fma2(acc[11], wb.y, q1.y);
        fma2(acc[12], wb.x, q2.x); fma2(acc[13], wb.y, q2.y);
        fma2(acc[14], wb.x, q3.x); fma2(acc[15], wb.y, q3.y);
    }
}

// ---------------------------------------------------------------------------
__global__ __launch_bounds__(256, 1)
void fused_lstm_kernel(const float* __restrict__ x,
                       const float* __restrict__ W_ih1,
                       const float* __restrict__ W_hh1,
                       const float* __restrict__ b_ih1,
                       const float* __restrict__ b_hh1,
                       const float* __restrict__ W_ih2,
                       const float* __restrict__ W_hh2,
                       const float* __restrict__ b_ih2,
                       const float* __restrict__ b_hh2,
                       const float* __restrict__ W_fc1,
                       const float* __restrict__ b_fc1,
                       const float* __restrict__ W_fc2,
                       const float* __restrict__ b_fc2,
                       float* __restrict__ out)
{
    extern __shared__ float sm[];
    const int tid = threadIdx.x;

    if (blockIdx.x < NP) {
        // ================= PRODUCER: layer 1, 4 batch elems =================
        const int pb = blockIdx.x;
        const int bg = pb * BBP;
        float* Ws = sm + P_WS;
        float* xs = sm + P_XS;
        float* hs = sm + P_HS;
        float* gs = sm + P_GS;

        // rows owned: rA = tid, rB = tid + 256
        const int rA = tid, rB = tid + 256;

        // smem weights: cols [0,64) of every row
        for (int i = tid; i < G1 * 64; i += 256) {
            int r = i >> 6, c = i & 63;
            Ws[r * P_PITCH + c] = W_hh1[r * H1 + c];
        }
        // reg weights: cols [64,128) of rows rA, rB
        ulonglong2 wrA[16], wrB[16];
        {
            const ulonglong2* sA = reinterpret_cast<const ulonglong2*>(W_hh1 + rA * H1 + 64);
            const ulonglong2* sB = reinterpret_cast<const ulonglong2*>(W_hh1 + rB * H1 + 64);
            #pragma unroll
            for (int j = 0; j < 16; j++) { wrA[j] = sA[j]; wrB[j] = sB[j]; }
        }
        const float wxA = W_ih1[rA], wxB = W_ih1[rB];
        const float bA  = b_ih1[rA] + b_hh1[rA];
        const float bB  = b_ih1[rB] + b_hh1[rB];

        for (int i = tid; i < BBP * T; i += 256)
            xs[i] = x[(size_t)bg * T + i];
        hs[tid] = 0.0f; hs[tid + 256] = 0.0f;
        __syncthreads();

        // update-state: slots s0=tid (bb=tid>>7), s1=tid+256 (bb+2)
        float cst0 = 0.0f, cst1 = 0.0f;
        const int ub = tid >> 7;         // 0..1
        const int um = tid & (H1 - 1);
        const bool isgB = (tid < 128);   // rB in [256,384) -> g gate

        const ulonglong2* wsA = reinterpret_cast<const ulonglong2*>(Ws + rA * P_PITCH);
        const ulonglong2* wsB = reinterpret_cast<const ulonglong2*>(Ws + rB * P_PITCH);

        for (int t = 0; t < T; t++) {
            unsigned long long acc[16];
            #pragma unroll
            for (int j = 0; j < 16; j++) acc[j] = 0ull;

            dot4x2<16>(wsA, wsB, hs, hs + 128, hs + 256, hs + 384, acc);      // k [0,64)
            dot4x2<16>(wrA, wrB, hs + 64, hs + 192, hs + 320, hs + 448, acc); // k [64,128)

            #pragma unroll
            for (int bb = 0; bb < BBP; bb++) {
                float xv = xs[bb * T + t];
                float fA = fmaf(xv, wxA, bA) + f32x2_sum2(acc[2 * bb],     acc[2 * bb + 1]);
                float fB = fmaf(xv, wxB, bB) + f32x2_sum2(acc[8 + 2 * bb], acc[8 + 2 * bb + 1]);
                // rA in [0,256): i/f gates -> sigmoid always
                gs[bb * G1 + rA] = sigmoid_fast(fA);
                gs[bb * G1 + rB] = isgB ? tanh_acc(fB) : sigmoid_fast(fB);
            }
            __syncthreads();

            // update: 2 slots per thread: (ub, um) and (ub+2, um)
            {
                const float* g0 = gs + ub * G1;
                float i0 = g0[um], f0 = g0[H1 + um], gg0 = g0[2 * H1 + um], o0 = g0[3 * H1 + um];
                cst0 = fmaf(f0, cst0, i0 * gg0);
                float h0v = o0 * tanh_acc(cst0);
                hs[tid] = h0v;
                g_h1seq[((size_t)(bg + ub) * T + t) * H1 + um] = h0v;

                const float* g1 = gs + (ub + 2) * G1;
                float i1 = g1[um], f1 = g1[H1 + um], gg1 = g1[2 * H1 + um], o1 = g1[3 * H1 + um];
                cst1 = fmaf(f1, cst1, i1 * gg1);
                float h1v = o1 * tanh_acc(cst1);
                hs[tid + 256] = h1v;
                g_h1seq[((size_t)(bg + ub + 2) * T + t) * H1 + um] = h1v;
            }
            __syncthreads();
            if (tid == 0) st_release(&g_flag[pb], t + 1);
        }

        // end handshake: wait for consumer, then reset flags for next replay
        if (tid == 0) {
            while (ld_acquire(&g_done[pb]) == 0) { }
            g_flag[pb] = 0;
            g_done[pb] = 0;
        }
    } else {
        // ================= CONSUMER: layer 2 + FC, 4 batch elems ============
        const int cb = blockIdx.x - NP;
        const int bg = cb * BBP;
        float* Ws2   = sm + C_WS;
        float* hcat  = sm + C_HC;     // [4][192] : h1 | h2
        float* gs2   = sm + C_GS;     // [4][256]
        float* bsm   = sm + C_BS;
        float* stage = sm + C_ST;

        const int r = tid;            // gate row 0..255

        // reg weights: concat row [0,160) = W_ih2[r][0:128) + W_hh2[r][0:32)
        ulonglong2 wr[40];
        {
            const ulonglong2* sa = reinterpret_cast<const ulonglong2*>(W_ih2 + r * H1);
            #pragma unroll
            for (int j = 0; j < 32; j++) wr[j] = sa[j];
            const ulonglong2* sb = reinterpret_cast<const ulonglong2*>(W_hh2 + r * H2);
            #pragma unroll
            for (int j = 0; j < 8; j++) wr[32 + j] = sb[j];
        }
        // smem weights: concat [160,192) = W_hh2[r][32:64)
        {
            float* wrow = Ws2 + tid * C_PITCH;
            const float4* src = reinterpret_cast<const float4*>(W_hh2 + r * H2 + 32);
            #pragma unroll
            for (int j = 0; j < 8; j++)
                reinterpret_cast<float4*>(wrow)[j] = src[j];
        }
        bsm[tid] = b_ih2[tid] + b_hh2[tid];
        // zero h2 region
        {
            int bb = tid >> 6, m = tid & (H2 - 1);
            hcat[bb * 192 + H1 + m] = 0.0f;
        }
        __syncthreads();

        float cst = 0.0f;                 // update state for (tid>>6, tid&63)
        const int ub = tid >> 6;
        const int um = tid & (H2 - 1);
        const bool is_g = (r >= 2 * H2) && (r < 3 * H2);
        const ulonglong2* ws = reinterpret_cast<const ulonglong2*>(Ws2 + tid * C_PITCH);

        for (int t = 0; t < T; t++) {
            if (tid == 0) {
                while (ld_acquire(&g_flag[cb]) < t + 1) { }
            }
            __syncthreads();

            // stage h1(t): 2 slots per thread
            {
                int s0 = tid, s1 = tid + 256;
                int b0 = s0 >> 7, m0 = s0 & (H1 - 1);
                int b1 = s1 >> 7, m1 = s1 & (H1 - 1);
                hcat[b0 * 192 + m0] = __ldcg(&g_h1seq[((size_t)(bg + b0) * T + t) * H1 + m0]);
                hcat[b1 * 192 + m1] = __ldcg(&g_h1seq[((size_t)(bg + b1) * T + t) * H1 + m1]);
            }
            __syncthreads();

            unsigned long long acc[8];
            #pragma unroll
            for (int j = 0; j < 8; j++) acc[j] = 0ull;
            dot4<40>(wr, hcat, hcat + 192, hcat + 384, hcat + 576, acc);            // k [0,160)
            dot4<8>(ws, hcat + 160, hcat + 352, hcat + 544, hcat + 736, acc);       // k [160,192)

            #pragma unroll
            for (int bb = 0; bb < BBP; bb++) {
                float v = bsm[r] + f32x2_sum2(acc[2 * bb], acc[2 * bb + 1]);
                gs2[bb * G2 + r] = is_g ? tanh_acc(v) : sigmoid_fast(v);
            }
            __syncthreads();

            // update: one (bb,m) slot per thread
            {
                const float* g0 = gs2 + ub * G2;
                float i_ = g0[um], f_ = g0[H2 + um], gg = g0[2 * H2 + um], o_ = g0[3 * H2 + um];
                cst = fmaf(f_, cst, i_ * gg);
                hcat[ub * 192 + H1 + um] = o_ * tanh_acc(cst);
            }
            __syncthreads();
        }

        // ---- FC head on final h2 ----
        if (tid < BBP * 25) {
            int bb = tid / 25;
            int i  = tid - bb * 25;
            float a = b_fc1[i];
            #pragma unroll
            for (int k = 0; k < H2; k++)
                a = fmaf(W_fc1[i * H2 + k], hcat[bb * 192 + H1 + k], a);
            stage[bb * 32 + i] = a;
        }
        __syncthreads();
        if (tid < BBP) {
            float a = b_fc2[0];
            #pragma unroll
            for (int i = 0; i < 25; i++)
                a = fmaf(W_fc2[i], stage[tid * 32 + i], a);
            out[bg + tid] = a;
        }
        if (tid == 0) st_release(&g_done[cb], 1);
    }
}

// ---------------------------------------------------------------------------
extern "C" void kernel_launch(void* const* d_in, const int* in_sizes, int n_in,
                              void* d_out, int out_size)
{
    const float* x     = (const float*)d_in[0];
    const float* W_ih1 = (const float*)d_in[1];
    const float* W_hh1 = (const float*)d_in[2];
    const float* b_ih1 = (const float*)d_in[3];
    const float* b_hh1 = (const float*)d_in[4];
    const float* W_ih2 = (const float*)d_in[5];
    const float* W_hh2 = (const float*)d_in[6];
    const float* b_ih2 = (const float*)d_in[7];
    const float* b_hh2 = (const float*)d_in[8];
    const float* W_fc1 = (const float*)d_in[9];
    const float* b_fc1 = (const float*)d_in[10];
    const float* W_fc2 = (const float*)d_in[11];
    const float* b_fc2 = (const float*)d_in[12];
    float* out = (float*)d_out;

    static bool attr_done = false;
    if (!attr_done) {
        cudaFuncSetAttribute(fused_lstm_kernel,
                             cudaFuncAttributeMaxDynamicSharedMemorySize, (int)SMEM_MAX);
        attr_done = true;
    }

    fused_lstm_kernel<<<NP + NC, 256, SMEM_MAX>>>(
        x, W_ih1, W_hh1, b_ih1, b_hh1,
        W_ih2, W_hh2, b_ih2, b_hh2,
        W_fc1, b_fc1, W_fc2, b_fc2, out);
}